// round 6
// baseline (speedup 1.0000x reference)
#include <cuda_runtime.h>
#include <cuda_fp16.h>
#include <math.h>
#include <stdint.h>

#define NTOK 4096
#define DIM  1024
#define NEXP 8
#define HID  2048
#define NPAIR (NTOK * 2)

// ---------------- scratch ----------------------------------------------------
__device__ int   g_cnt[NEXP];
__device__ int   g_list[NEXP * NTOK];
__device__ float g_pw[NPAIR];
__device__ __half g_xh [(size_t)NTOK * 2 * DIM];            // [hi|lo]  16 MB
__device__ __half g_w1h[(size_t)NEXP * 2 * HID * DIM];      // hi only  67 MB
__device__ __half g_w2h[(size_t)NEXP * DIM * HID];          // hi only  33 MB
__device__ __half g_acth[(size_t)NPAIR * 2 * HID];          // [hi|lo]  67 MB
__device__ float g_y[(size_t)NPAIR * DIM];                  // 33 MB

// ---------------- helpers ----------------------------------------------------
__device__ __forceinline__ uint32_t smem_u32(const void* p) {
    uint32_t a;
    asm("{ .reg .u64 t; cvta.to.shared.u64 t, %1; cvt.u32.u64 %0, t; }" : "=r"(a) : "l"(p));
    return a;
}
__device__ __forceinline__ void ldsm4(uint32_t* r, uint32_t addr) {
    asm volatile("ldmatrix.sync.aligned.m8n8.x4.shared.b16 {%0,%1,%2,%3}, [%4];"
        : "=r"(r[0]), "=r"(r[1]), "=r"(r[2]), "=r"(r[3]) : "r"(addr));
}
__device__ __forceinline__ void mma16816(float* c, const uint32_t* a, uint32_t b0, uint32_t b1) {
    asm volatile("mma.sync.aligned.m16n8k16.row.col.f32.f16.f16.f32 "
        "{%0,%1,%2,%3}, {%4,%5,%6,%7}, {%8,%9}, {%0,%1,%2,%3};"
        : "+f"(c[0]), "+f"(c[1]), "+f"(c[2]), "+f"(c[3])
        : "r"(a[0]), "r"(a[1]), "r"(a[2]), "r"(a[3]), "r"(b0), "r"(b1));
}
#define SWZ(o) ((o) ^ (((o) >> 3) & 0x70))
#define CP16(dst, src) asm volatile("cp.async.cg.shared.global [%0], [%1], 16;" :: "r"(dst), "l"(src))
#define CP_COMMIT() asm volatile("cp.async.commit_group;")
#define CP_WAIT1()  asm volatile("cp.async.wait_group 1;")
#define CP_WAIT0()  asm volatile("cp.async.wait_group 0;")

// smem: base 1024-aligned; sp[128] @ base; 3 stages @ base+1024 + s*49152,
// stage = A(16KB) + B(32KB). Epilogue S(float, 128x257) reuses stage space.
#define STAGE_BYTES 49152
#define SMEM_BYTES  (1024 + 1024 + 3 * STAGE_BYTES)

// ---------------- init / router ----------------------------------------------
__global__ void init_kernel() {
    if (threadIdx.x < NEXP) g_cnt[threadIdx.x] = 0;
}

__global__ void router_kernel(const float* __restrict__ x,
                              const float* __restrict__ gw,
                              float* __restrict__ logits) {
    __shared__ float sgw[NEXP * DIM];
    for (int i = threadIdx.x; i < NEXP * DIM; i += blockDim.x) sgw[i] = gw[i];
    __syncthreads();
    int warp = threadIdx.x >> 5, lane = threadIdx.x & 31;
    int n = blockIdx.x * (blockDim.x >> 5) + warp;
    if (n >= NTOK) return;
    const float* xr = x + (size_t)n * DIM;
    float acc[NEXP];
#pragma unroll
    for (int e = 0; e < NEXP; e++) acc[e] = 0.f;
    for (int k = lane; k < DIM; k += 32) {
        float xv = xr[k];
#pragma unroll
        for (int e = 0; e < NEXP; e++) acc[e] += xv * sgw[e * DIM + k];
    }
#pragma unroll
    for (int e = 0; e < NEXP; e++)
#pragma unroll
        for (int off = 16; off; off >>= 1)
            acc[e] += __shfl_xor_sync(0xffffffffu, acc[e], off);
    if (lane == 0) {
        int a = 0;
#pragma unroll
        for (int e = 1; e < NEXP; e++) if (acc[e] > acc[a]) a = e;
        int b = (a == 0) ? 1 : 0;
#pragma unroll
        for (int e = 0; e < NEXP; e++) {
            if (e == a || e == b) continue;
            if (acc[e] > acc[b]) b = e;
        }
        float eb = expf(acc[b] - acc[a]);
        float inv = 1.f / (1.f + eb);
        g_pw[n * 2 + 0] = inv;
        g_pw[n * 2 + 1] = eb * inv;
        int pa = atomicAdd(&g_cnt[a], 1); g_list[a * NTOK + pa] = n * 2 + 0;
        int pb = atomicAdd(&g_cnt[b], 1); g_list[b * NTOK + pb] = n * 2 + 1;
#pragma unroll
        for (int e = 0; e < NEXP; e++) logits[(size_t)n * NEXP + e] = acc[e];
    }
}

// ---------------- conversions -------------------------------------------------
__device__ __forceinline__ void split_h(float v, __half& hi, __half& lo) {
    hi = __float2half(v);
    lo = __float2half(v - __half2float(hi));
}

__global__ void convert_x_kernel(const float* __restrict__ x) {
    int i = blockIdx.x * blockDim.x + threadIdx.x;
    if (i >= NTOK * DIM / 4) return;
    int n = i >> 8;
    int k = (i & 255) * 4;
    float4 v = *(const float4*)(x + (size_t)n * DIM + k);
    __half h[4], l[4];
    split_h(v.x, h[0], l[0]); split_h(v.y, h[1], l[1]);
    split_h(v.z, h[2], l[2]); split_h(v.w, h[3], l[3]);
    __half* o = g_xh + (size_t)n * (2 * DIM) + k;
#pragma unroll
    for (int j = 0; j < 4; j++) { o[j] = h[j]; o[DIM + j] = l[j]; }
}

// w1 [E, D(k), 4096(n)] -> g_w1h [E, n, D] hi only (transpose)
__global__ void convert_w1_kernel(const float* __restrict__ w1) {
    __shared__ float t[32][33];
    int e = blockIdx.z, n0 = blockIdx.x * 32, k0 = blockIdx.y * 32;
    int tx = threadIdx.x, ty = threadIdx.y;
    const float* src = w1 + (size_t)e * DIM * (2 * HID);
#pragma unroll
    for (int j = 0; j < 4; j++) {
        int kk = ty + j * 8;
        t[kk][tx] = src[(size_t)(k0 + kk) * (2 * HID) + n0 + tx];
    }
    __syncthreads();
#pragma unroll
    for (int j = 0; j < 4; j++) {
        int nn = ty + j * 8;
        g_w1h[((size_t)e * (2 * HID) + n0 + nn) * DIM + k0 + tx] = __float2half(t[tx][nn]);
    }
}

// w2 [E, H(k), D(n)] -> g_w2h [E, n, H] hi only
__global__ void convert_w2_kernel(const float* __restrict__ w2) {
    __shared__ float t[32][33];
    int e = blockIdx.z, n0 = blockIdx.x * 32, k0 = blockIdx.y * 32;
    int tx = threadIdx.x, ty = threadIdx.y;
    const float* src = w2 + (size_t)e * HID * DIM;
#pragma unroll
    for (int j = 0; j < 4; j++) {
        int kk = ty + j * 8;
        t[kk][tx] = src[(size_t)(k0 + kk) * DIM + n0 + tx];
    }
    __syncthreads();
#pragma unroll
    for (int j = 0; j < 4; j++) {
        int nn = ty + j * 8;
        g_w2h[((size_t)e * DIM + n0 + nn) * HID + k0 + tx] = __float2half(t[tx][nn]);
    }
}

// ---------------- mma.sync grouped GEMMs --------------------------------------
// 128x256 block tile, 256 threads = 8 warps (2m x 4n), warp tile 64x64.
// A logical K' = 2K [hi|lo] (stored directly); B logical [hi|hi] (dup via offset).

#define LOADT(c, offb, s) do {                                       \
    _Pragma("unroll") for (int i = 0; i < 4; i++)                    \
        CP16(Ab_[s] + dstA[i], aptr[i] + (size_t)(c) * 128);         \
    _Pragma("unroll") for (int i = 0; i < 8; i++)                    \
        CP16(Bb_[s] + dstB[i], bptr[i] + (offb));                    \
    CP_COMMIT(); } while (0)

#define GEMM_CORE(NC, OFFB)                                                   \
    const int l = tid & 31, wid = tid >> 5;                                   \
    const int wm = (wid >> 2) * 64, wn = (wid & 3) * 64;                      \
    const int mA = (l & 7) | (((l >> 3) & 1) << 3);                           \
    const int khA = (l >> 4) & 1;                                             \
    const int nB = (l & 7) | (((l >> 4) & 1) << 3);                           \
    const int khB = (l >> 3) & 1;                                             \
    uint32_t aRow[4], bRow[4], kxA[4], kxB[4];                                \
    _Pragma("unroll") for (int mt = 0; mt < 4; mt++)                          \
        aRow[mt] = (wm + mt * 16 + mA) * 128;                                 \
    _Pragma("unroll") for (int jj = 0; jj < 4; jj++)                          \
        bRow[jj] = (wn + jj * 16 + nB) * 128;                                 \
    _Pragma("unroll") for (int ks = 0; ks < 4; ks++) {                        \
        kxA[ks] = ((uint32_t)(ks * 32 + khA * 16)) ^ (((uint32_t)(l & 7)) << 4); \
        kxB[ks] = ((uint32_t)(ks * 32 + khB * 16)) ^ (((uint32_t)(l & 7)) << 4); \
    }                                                                         \
    float acc[4][8][4];                                                       \
    _Pragma("unroll") for (int a = 0; a < 4; a++)                             \
    _Pragma("unroll") for (int b = 0; b < 8; b++)                             \
    _Pragma("unroll") for (int q = 0; q < 4; q++) acc[a][b][q] = 0.f;         \
    LOADT(0, OFFB(0), 0);                                                     \
    LOADT(1, OFFB(1), 1);                                                     \
    for (int c = 0; c < (NC); c++) {                                          \
        int s = c % 3;                                                        \
        if (c == (NC) - 1) CP_WAIT0(); else CP_WAIT1();                       \
        __syncthreads();                                                      \
        if (c + 2 < (NC)) { int s2 = (c + 2) % 3; LOADT(c + 2, OFFB(c + 2), s2); } \
        uint32_t As = Ab_[s], Bs = Bb_[s];                                    \
        _Pragma("unroll") for (int ks = 0; ks < 4; ks++) {                    \
            uint32_t afr[4][4], bfr[4][4];                                    \
            _Pragma("unroll") for (int mt = 0; mt < 4; mt++)                  \
                ldsm4(afr[mt], As + aRow[mt] + kxA[ks]);                      \
            _Pragma("unroll") for (int jj = 0; jj < 4; jj++)                  \
                ldsm4(bfr[jj], Bs + bRow[jj] + kxB[ks]);                      \
            _Pragma("unroll") for (int mt = 0; mt < 4; mt++)                  \
            _Pragma("unroll") for (int jj = 0; jj < 4; jj++) {                \
                mma16816(acc[mt][2 * jj],     afr[mt], bfr[jj][0], bfr[jj][1]); \
                mma16816(acc[mt][2 * jj + 1], afr[mt], bfr[jj][2], bfr[jj][3]); \
            }                                                                 \
        }                                                                     \
    }

#define OFFB1(c) ((size_t)(((c) < 16 ? (c) : (c) - 16)) * 128)
#define OFFB2(c) ((size_t)(((c) < 32 ? (c) : (c) - 32)) * 128)

__global__ __launch_bounds__(256)
void gemm1_mma() {
    int e = blockIdx.z;
    int cnt = g_cnt[e];
    int row0 = blockIdx.y * 128;
    if (row0 >= cnt) return;
    int hcol0 = blockIdx.x * 128;

    extern __shared__ char sm[];
    uint32_t raw = smem_u32(sm);
    uint32_t base = (raw + 1023u) & ~1023u;
    char* smc = sm + (base - raw);
    int* sp = (int*)smc;
    uint32_t Ab_[3], Bb_[3];
#pragma unroll
    for (int s = 0; s < 3; s++) {
        Ab_[s] = base + 1024 + s * STAGE_BYTES;
        Bb_[s] = Ab_[s] + 16384;
    }

    int tid = threadIdx.x;
    if (tid < 128) sp[tid] = g_list[e * NTOK + min(row0 + tid, cnt - 1)];
    __syncthreads();

    // loaders: A 4 pieces (rows tid>>3 + 32i), B 8 pieces (rows 0..255)
    int seg = tid & 7, rb = tid >> 3;
    const char* w1e = (const char*)(g_w1h + (size_t)e * (2 * HID) * DIM);
    const char* aptr[4]; const char* bptr[8]; uint32_t dstA[4], dstB[8];
#pragma unroll
    for (int i = 0; i < 4; i++) {
        int r = rb + 32 * i;
        dstA[i] = SWZ(r * 128 + seg * 16);
        int tok = sp[r] >> 1;
        aptr[i] = (const char*)g_xh + (size_t)tok * (2 * DIM) * 2 + seg * 16;
    }
#pragma unroll
    for (int i = 0; i < 8; i++) {
        int r = rb + 32 * i;
        dstB[i] = SWZ(r * 128 + seg * 16);
        int nrow = (r < 128) ? (hcol0 + r) : (HID + hcol0 + (r - 128));
        bptr[i] = w1e + (size_t)nrow * DIM * 2 + seg * 16;
    }

    GEMM_CORE(32, OFFB1)

    // epilogue: acc -> S[128][257] (cols 0..127 g, 128..255 lin) -> SwiGLU
    __syncthreads();
    float* S = (float*)(smc + 1024);
#pragma unroll
    for (int mt = 0; mt < 4; mt++) {
        int m0 = wm + mt * 16 + (l >> 2);
#pragma unroll
        for (int j = 0; j < 8; j++) {
            int n = wn + j * 8 + (l & 3) * 2;
            S[m0 * 257 + n]     = acc[mt][j][0];
            S[m0 * 257 + n + 1] = acc[mt][j][1];
            S[(m0 + 8) * 257 + n]     = acc[mt][j][2];
            S[(m0 + 8) * 257 + n + 1] = acc[mt][j][3];
        }
    }
    __syncthreads();
    {
        int m = tid >> 1;
        int hb = (tid & 1) * 64;
        if (row0 + m < cnt) {
            int p = sp[m];
            __half* ab = g_acth + (size_t)p * (2 * HID) + hcol0;
#pragma unroll
            for (int u = 0; u < 64; u++) {
                int h = hb + u;
                float gv = S[m * 257 + h];
                float lv = S[m * 257 + 128 + h];
                float v = (gv / (1.f + expf(-gv))) * lv;
                __half hi, lo; split_h(v, hi, lo);
                ab[h] = hi; ab[HID + h] = lo;
            }
        }
    }
}

__global__ __launch_bounds__(256)
void gemm2_mma() {
    int e = blockIdx.z;
    int cnt = g_cnt[e];
    int row0 = blockIdx.y * 128;
    if (row0 >= cnt) return;
    int n0 = blockIdx.x * 256;

    extern __shared__ char sm[];
    uint32_t raw = smem_u32(sm);
    uint32_t base = (raw + 1023u) & ~1023u;
    char* smc = sm + (base - raw);
    int* sp = (int*)smc;
    uint32_t Ab_[3], Bb_[3];
#pragma unroll
    for (int s = 0; s < 3; s++) {
        Ab_[s] = base + 1024 + s * STAGE_BYTES;
        Bb_[s] = Ab_[s] + 16384;
    }

    int tid = threadIdx.x;
    if (tid < 128) sp[tid] = g_list[e * NTOK + min(row0 + tid, cnt - 1)];
    __syncthreads();

    int seg = tid & 7, rb = tid >> 3;
    const char* w2e = (const char*)(g_w2h + (size_t)e * DIM * HID);
    const char* aptr[4]; const char* bptr[8]; uint32_t dstA[4], dstB[8];
#pragma unroll
    for (int i = 0; i < 4; i++) {
        int r = rb + 32 * i;
        dstA[i] = SWZ(r * 128 + seg * 16);
        int p = sp[r];
        aptr[i] = (const char*)g_acth + (size_t)p * (2 * HID) * 2 + seg * 16;
    }
#pragma unroll
    for (int i = 0; i < 8; i++) {
        int r = rb + 32 * i;
        dstB[i] = SWZ(r * 128 + seg * 16);
        bptr[i] = w2e + (size_t)(n0 + r) * HID * 2 + seg * 16;
    }

    GEMM_CORE(64, OFFB2)

    // epilogue: fragments straight to g_y
#pragma unroll
    for (int mt = 0; mt < 4; mt++) {
        int mloc = wm + mt * 16 + (l >> 2);
#pragma unroll
        for (int half = 0; half < 2; half++) {
            int m = mloc + half * 8;
            if (row0 + m < cnt) {
                int p = sp[m];
                float* yp = g_y + (size_t)p * DIM + n0 + wn + (l & 3) * 2;
#pragma unroll
                for (int j = 0; j < 8; j++) {
                    float2 v;
                    v.x = acc[mt][j][half * 2 + 0];
                    v.y = acc[mt][j][half * 2 + 1];
                    *(float2*)(yp + j * 8) = v;
                }
            }
        }
    }
}

// ---------------- combine ----------------------------------------------------
__global__ void combine_kernel(float* __restrict__ out) {
    int i = blockIdx.x * blockDim.x + threadIdx.x;
    if (i >= NTOK * DIM / 4) return;
    int n  = i / (DIM / 4);
    int c4 = (i % (DIM / 4)) * 4;
    float w0 = g_pw[2 * n];
    float w1 = g_pw[2 * n + 1];
    float4 y0 = *(const float4*)(g_y + (size_t)(2 * n) * DIM + c4);
    float4 y1 = *(const float4*)(g_y + (size_t)(2 * n + 1) * DIM + c4);
    float4 o;
    o.x = w0 * y0.x + w1 * y1.x;
    o.y = w0 * y0.y + w1 * y1.y;
    o.z = w0 * y0.z + w1 * y1.z;
    o.w = w0 * y0.w + w1 * y1.w;
    *(float4*)(out + (size_t)n * DIM + c4) = o;
}

// ---------------- launch -----------------------------------------------------
extern "C" void kernel_launch(void* const* d_in, const int* in_sizes, int n_in,
                              void* d_out, int out_size) {
    const float* x  = (const float*)d_in[0];
    const float* gw = (const float*)d_in[1];
    const float* w1 = (const float*)d_in[2];
    const float* w2 = (const float*)d_in[3];
    float* out    = (float*)d_out;
    float* logits = out + (size_t)NTOK * DIM;

    cudaFuncSetAttribute(gemm1_mma, cudaFuncAttributeMaxDynamicSharedMemorySize, SMEM_BYTES);
    cudaFuncSetAttribute(gemm2_mma, cudaFuncAttributeMaxDynamicSharedMemorySize, SMEM_BYTES);

    init_kernel<<<1, 32>>>();
    router_kernel<<<NTOK / 8, 256>>>(x, gw, logits);

    convert_x_kernel<<<(NTOK * DIM / 4 + 255) / 256, 256>>>(x);
    convert_w1_kernel<<<dim3(2 * HID / 32, DIM / 32, NEXP), dim3(32, 8)>>>(w1);
    convert_w2_kernel<<<dim3(DIM / 32, HID / 32, NEXP), dim3(32, 8)>>>(w2);

    gemm1_mma<<<dim3(HID / 128, NTOK / 128, NEXP), 256, SMEM_BYTES>>>();
    gemm2_mma<<<dim3(DIM / 256, NTOK / 128, NEXP), 256, SMEM_BYTES>>>();

    combine_kernel<<<(NTOK * DIM / 4 + 255) / 256, 256>>>(out);
}